// round 8
// baseline (speedup 1.0000x reference)
#include <cuda_runtime.h>
#include <cuda_fp16.h>
#include <cstdint>

// TrainableActivation (per-channel RBF activation) on GB300 — round 8.
//
// out[n,c,h,w] = sum_{j=0..30} w[c,j] * exp(-112.5 * (x - mu_j)^2)
//
// Round-8: bulk-async (TMA-style) streaming. Rounds 5-7 pinned at ~19.5us
// with no pipe >56% -> suspect per-thread LDG/STG issue+latency. Replace:
//  * input: cp.async.bulk G->SMEM, 3-stage 4KB ring behind mbarriers
//  * output: cp.async.bulk SMEM->G, 2 buffers, bulk_group wait for reuse
//  * compute: conflict-free LDS.128 in / STS.128 out + 4-way replicated
//    fp16 LUT gather (unchanged), SAT-clamp indexing
//  * LUT (512-entry, Gaussian-lattice recurrence build) hides under the
//    prologue DMA. smem ~31KB -> 7 blocks/SM, 1024 blocks fully resident.

#define NUM_CH   64
#define NUM_W    31
#define LUT_N    512
#define REP      4
#define HW       16384            // 128*128 floats per plane
#define NBATCH   16

#define TILE_FLOATS   1024        // 4 KB tiles
#define TILE_BYTES    4096
#define NTILES        16          // one plane = 16 tiles
#define NSTAGE_IN     3

// ---- bulk-async + mbarrier primitives -------------------------------------
__device__ __forceinline__ unsigned smem_u32(const void* p)
{
    return (unsigned)__cvta_generic_to_shared(p);
}
__device__ __forceinline__ void mbar_init(unsigned mbar, unsigned count)
{
    asm volatile("mbarrier.init.shared.b64 [%0], %1;" :: "r"(mbar), "r"(count) : "memory");
}
__device__ __forceinline__ void mbar_expect_tx(unsigned mbar, unsigned bytes)
{
    asm volatile("mbarrier.arrive.expect_tx.shared.b64 _, [%0], %1;"
                 :: "r"(mbar), "r"(bytes) : "memory");
}
__device__ __forceinline__ void mbar_wait_parity(unsigned mbar, unsigned phase)
{
    unsigned done;
    asm volatile(
        "{\n\t.reg .pred p;\n\t"
        "mbarrier.try_wait.parity.acquire.cta.shared::cta.b64 p, [%1], %2;\n\t"
        "selp.b32 %0, 1, 0, p;\n\t}"
        : "=r"(done) : "r"(mbar), "r"(phase) : "memory");
    if (!done) {
        asm volatile(
            "{\n\t.reg .pred P1;\n\t"
            "WL_%=:\n\t"
            "mbarrier.try_wait.parity.acquire.cta.shared::cta.b64 P1, [%0], %1, 0x989680;\n\t"
            "@P1 bra.uni WD_%=;\n\t"
            "bra.uni WL_%=;\n\t"
            "WD_%=:\n\t}"
            :: "r"(mbar), "r"(phase) : "memory");
    }
}
__device__ __forceinline__ void bulk_load(unsigned dst_smem, const void* src_gmem,
                                          unsigned bytes, unsigned mbar)
{
    asm volatile(
        "cp.async.bulk.shared::cluster.global.mbarrier::complete_tx::bytes "
        "[%0], [%1], %2, [%3];"
        :: "r"(dst_smem), "l"(src_gmem), "r"(bytes), "r"(mbar) : "memory");
}
__device__ __forceinline__ void bulk_store(void* dst_gmem, unsigned src_smem,
                                           unsigned bytes)
{
    asm volatile("cp.async.bulk.global.shared::cta.bulk_group [%0], [%1], %2;"
                 :: "l"(dst_gmem), "r"(src_smem), "r"(bytes) : "memory");
    asm volatile("cp.async.bulk.commit_group;");
}
template <int N>
__device__ __forceinline__ void bulk_store_wait()
{
    asm volatile("cp.async.bulk.wait_group %0;" :: "n"(N) : "memory");
}
__device__ __forceinline__ void fence_async_shared()
{
    asm volatile("fence.proxy.async.shared::cta;" ::: "memory");
}

// ---------------------------------------------------------------------------
__global__ void __launch_bounds__(256)
fused_rbf_kernel(const float* __restrict__ x,
                 float* __restrict__ y,
                 const float* __restrict__ w)
{
    __shared__ __align__(16) __half2 lut[LUT_N * REP];           //  8 KB
    __shared__ float fv[LUT_N + 1];                              //  2 KB
    __shared__ float ws[NUM_W];
    __shared__ __align__(16) float in_buf[NSTAGE_IN][TILE_FLOATS];  // 12 KB
    __shared__ __align__(16) float out_buf[2][TILE_FLOATS];         //  8 KB
    __shared__ __align__(8) uint64_t mbar[NSTAGE_IN];

    const int c   = blockIdx.x;
    const int n   = blockIdx.y;
    const int tid = threadIdx.x;

    const float* src = x + (size_t)(n * NUM_CH + c) * HW;
    float*       dst = y + (size_t)(n * NUM_CH + c) * HW;

    // ---- init mbarriers + fetch weights ----------------------------------
    if (tid == 0) {
#pragma unroll
        for (int s = 0; s < NSTAGE_IN; s++) mbar_init(smem_u32(&mbar[s]), 1);
    }
    if (tid < NUM_W) ws[tid] = w[c * NUM_W + tid];
    __syncthreads();

    // ---- prologue: launch the first 3 tile DMAs (DRAM busy immediately) --
    if (tid == 0) {
#pragma unroll
        for (int s = 0; s < NSTAGE_IN; s++) {
            const unsigned mb = smem_u32(&mbar[s]);
            mbar_expect_tx(mb, TILE_BYTES);
            bulk_load(smem_u32(&in_buf[s][0]), src + s * TILE_FLOATS, TILE_BYTES, mb);
        }
    }

    // ---- build this channel's LUT (hides under the DMA latency) ----------
    // f at 513 points over [-1.5,1.5]; 11-center window + lattice recurrence
    // (sigma == spacing): g_{j+1} = g_j*r_j, r_{j+1} = r_j*e^-1.
    const float h = 3.0f / (float)(LUT_N - 1);
    for (int k = tid; k < LUT_N + 1; k += 256) {
        const float xx = fmaf((float)k, h, -1.5f);
        int j0 = (int)ceilf((xx + 1.0f) * 15.0f - 5.4f);
        j0 = min(20, max(0, j0));
        const float u0 = xx - fmaf((float)j0, 1.0f / 15.0f, -1.0f);

        float g = __expf(-112.5f * u0 * u0);
        float r = __expf(fmaf(15.0f, u0, -0.5f));
        float s = 0.0f;
#pragma unroll
        for (int m = 0; m < 11; m++) {
            s = fmaf(ws[j0 + m], g, s);
            g *= r;
            r *= 0.36787944f;   // e^-1
        }
        fv[k] = s;
    }
    __syncthreads();

    // Pack (value, forward-delta) half2, replicate 4-way (words 4i..4i+3).
#pragma unroll
    for (int m = 0; m < LUT_N / 256; m++) {
        const int i = tid + 256 * m;
        __half2 e = __floats2half2_rn(fv[i], fv[i + 1] - fv[i]);
        const unsigned u = *reinterpret_cast<unsigned*>(&e);
        reinterpret_cast<uint4*>(lut)[i] = make_uint4(u, u, u, u);
    }
    __syncthreads();

    // ---- main loop: 16 tiles, 3-stage in-ring, 2 out-buffers -------------
    const float INV3  = 1.0f / 3.0f;
    const float TMAX  = (float)(LUT_N - 1);
    const __half2* lp = lut + (tid & 3);

#pragma unroll
    for (int t = 0; t < NTILES; t++) {
        const int s  = t % NSTAGE_IN;
        const int b  = t & 1;
        const unsigned ph = (unsigned)((t / NSTAGE_IN) & 1);

        // Data for tile t has landed?
        mbar_wait_parity(smem_u32(&mbar[s]), ph);

        // out_buf[b] free? (store issued at t-2 must have drained)
        if (t >= 2) {
            if (tid == 0) bulk_store_wait<1>();
            __syncthreads();
        }

        // consume: one float4 per thread, conflict-free
        const float4 v = reinterpret_cast<const float4*>(in_buf[s])[tid];
        float4 o;
        {
            const float tt = __saturatef(fmaf(v.x, INV3, 0.5f)) * TMAX;
            const int idx = (int)tt;
            const float2 e = __half22float2(lp[idx * REP]);
            o.x = fmaf(tt - (float)idx, e.y, e.x);
        }
        {
            const float tt = __saturatef(fmaf(v.y, INV3, 0.5f)) * TMAX;
            const int idx = (int)tt;
            const float2 e = __half22float2(lp[idx * REP]);
            o.y = fmaf(tt - (float)idx, e.y, e.x);
        }
        {
            const float tt = __saturatef(fmaf(v.z, INV3, 0.5f)) * TMAX;
            const int idx = (int)tt;
            const float2 e = __half22float2(lp[idx * REP]);
            o.z = fmaf(tt - (float)idx, e.y, e.x);
        }
        {
            const float tt = __saturatef(fmaf(v.w, INV3, 0.5f)) * TMAX;
            const int idx = (int)tt;
            const float2 e = __half22float2(lp[idx * REP]);
            o.w = fmaf(tt - (float)idx, e.y, e.x);
        }
        reinterpret_cast<float4*>(out_buf[b])[tid] = o;

        __syncthreads();   // all read in_buf[s]; all wrote out_buf[b]

        if (tid == 0) {
            // refill stage s with tile t+3
            if (t + NSTAGE_IN < NTILES) {
                const unsigned mb = smem_u32(&mbar[s]);
                mbar_expect_tx(mb, TILE_BYTES);
                bulk_load(smem_u32(&in_buf[s][0]),
                          src + (t + NSTAGE_IN) * TILE_FLOATS, TILE_BYTES, mb);
            }
            // flush tile t
            fence_async_shared();
            bulk_store(dst + t * TILE_FLOATS, smem_u32(&out_buf[b][0]), TILE_BYTES);
        }
    }

    // drain pending bulk stores before the CTA retires
    if (tid == 0) bulk_store_wait<0>();
}

// ---------------------------------------------------------------------------
// Launch: ONE kernel (graph-capturable, allocation-free, deterministic).
// ---------------------------------------------------------------------------
extern "C" void kernel_launch(void* const* d_in, const int* in_sizes, int n_in,
                              void* d_out, int out_size)
{
    const float* x = (const float*)d_in[0];   // [16, 64, 128, 128] fp32
    const float* w = (const float*)d_in[1];   // [64, 31] fp32

    fused_rbf_kernel<<<dim3(NUM_CH, NBATCH), 256>>>(x, (float*)d_out, w);
}